// round 1
// baseline (speedup 1.0000x reference)
#include <cuda_runtime.h>
#include <cuda_fp16.h>
#include <cstdint>

#define BB 8
#define NN 4096
#define FI 128
#define FO 64
#define BI 128
#define BJ 64
#define PPITCH 72
#define HPITCH 72

// Scratch (static __device__ — no allocation allowed)
__device__ __half h_fp16[(size_t)BB * NN * FO];   // 4 MB
__device__ float  s1_g[BB * NN];
__device__ float  s2_g[BB * NN];
__device__ float2 pq1_g[BB * NN];                 // {P1, Q1} per (b,i)
__device__ float2 pq2_g[BB * NN];                 // {P2, Q2} per (b,j)

// ---------------------------------------------------------------------------
// Kernel A1: h = inp @ W (fp32 compute, fp16 store), s1 = h@a1, s2 = h@a2
// 16 rows per CTA, 256 threads: thread (r = tid>>4, ox = tid&15) computes
// h[r][ox*4 .. ox*4+3].
// ---------------------------------------------------------------------------
__global__ __launch_bounds__(256) void k_h(const float* __restrict__ inp,
                                           const float* __restrict__ W,
                                           const float* __restrict__ a)
{
    __shared__ __align__(16) float W_sm[FI * FO];      // 32 KB
    __shared__ __align__(16) float inp_sm[16 * FI];    // 8 KB
    __shared__ float a_sm[2 * FO];

    const int tid = threadIdx.x;
    const int blk = blockIdx.x;                // 0 .. BB*NN/16-1
    const int b   = blk / (NN / 16);
    const int i0  = (blk % (NN / 16)) * 16;

    for (int k = tid; k < FI * FO / 4; k += 256)
        ((float4*)W_sm)[k] = ((const float4*)W)[k];
    if (tid < 2 * FO) a_sm[tid] = a[tid];
    const float* inp_b = inp + ((size_t)b * NN + i0) * FI;
    for (int k = tid; k < 16 * FI / 4; k += 256)
        ((float4*)inp_sm)[k] = ((const float4*)inp_b)[k];
    __syncthreads();

    const int ox = tid & 15;
    const int r  = tid >> 4;
    const float* irow = inp_sm + r * FI;
    const float4* Wv  = (const float4*)W_sm;

    float a0 = 0.f, a1v = 0.f, a2v = 0.f, a3 = 0.f;
#pragma unroll 8
    for (int f = 0; f < FI; f++) {
        float x = irow[f];
        float4 w = Wv[f * 16 + ox];
        a0 += x * w.x; a1v += x * w.y; a2v += x * w.z; a3 += x * w.w;
    }

    const int o4 = ox * 4;
    float s1p = a0 * a_sm[o4] + a1v * a_sm[o4 + 1] + a2v * a_sm[o4 + 2] + a3 * a_sm[o4 + 3];
    float s2p = a0 * a_sm[FO + o4] + a1v * a_sm[FO + o4 + 1] + a2v * a_sm[FO + o4 + 2] + a3 * a_sm[FO + o4 + 3];
#pragma unroll
    for (int m = 8; m >= 1; m >>= 1) {
        s1p += __shfl_xor_sync(0xffffffffu, s1p, m);
        s2p += __shfl_xor_sync(0xffffffffu, s2p, m);
    }
    const int grow = b * NN + i0 + r;
    if (ox == 0) { s1_g[grow] = s1p; s2_g[grow] = s2p; }

    __half2 h01 = __floats2half2_rn(a0, a1v);
    __half2 h23 = __floats2half2_rn(a2v, a3);
    __half2* dst = (__half2*)(h_fp16 + (size_t)grow * FO + o4);
    dst[0] = h01; dst[1] = h23;
}

// ---------------------------------------------------------------------------
// Kernel A2: per-b s2max reduction, then
//   M_i  = lrelu(s1L_i + s2maxL)           (L = log2 e; lrelu(x)*L = lrelu(x*L))
//   P1_i = 2^(s1L_i - M_i),  Q1_i = 2^(0.2*s1L_i - M_i)
//   P2_j = 2^(s2L_j),        Q2_j = 2^(0.2*s2L_j)
// so that  exp(lrelu(s1+s2) - M/L) = max(P1*P2, Q1*Q2)
// ---------------------------------------------------------------------------
__global__ void k_pq()
{
    const int b = blockIdx.x;
    const int tid = threadIdx.x;      // 512 threads
    __shared__ float red[16];

    const float* s2b = s2_g + b * NN;
    float mx = -1e30f;
    for (int j = tid; j < NN; j += 512) mx = fmaxf(mx, s2b[j]);
#pragma unroll
    for (int m = 16; m >= 1; m >>= 1)
        mx = fmaxf(mx, __shfl_xor_sync(0xffffffffu, mx, m));
    if ((tid & 31) == 0) red[tid >> 5] = mx;
    __syncthreads();
    if (tid == 0) {
        float v = red[0];
        for (int k = 1; k < 16; k++) v = fmaxf(v, red[k]);
        red[0] = v;
    }
    __syncthreads();

    const float L = 1.4426950408889634f;
    const float s2maxL = red[0] * L;
    for (int j = tid; j < NN; j += 512) {
        float sL = s2b[j] * L;
        pq2_g[b * NN + j] = make_float2(exp2f(sL), exp2f(0.2f * sL));
        float s1L = s1_g[b * NN + j] * L;
        float t = s1L + s2maxL;
        float M = fmaxf(t, 0.2f * t);
        pq1_g[b * NN + j] = make_float2(exp2f(s1L - M), exp2f(0.2f * s1L - M));
    }
}

// ---------------------------------------------------------------------------
// mma / ldmatrix helpers
// ---------------------------------------------------------------------------
__device__ __forceinline__ void ldsm4(uint32_t& r0, uint32_t& r1, uint32_t& r2, uint32_t& r3, uint32_t addr)
{
    asm volatile("ldmatrix.sync.aligned.m8n8.x4.shared.b16 {%0,%1,%2,%3}, [%4];"
                 : "=r"(r0), "=r"(r1), "=r"(r2), "=r"(r3) : "r"(addr));
}
__device__ __forceinline__ void ldsm4t(uint32_t& r0, uint32_t& r1, uint32_t& r2, uint32_t& r3, uint32_t addr)
{
    asm volatile("ldmatrix.sync.aligned.m8n8.x4.trans.shared.b16 {%0,%1,%2,%3}, [%4];"
                 : "=r"(r0), "=r"(r1), "=r"(r2), "=r"(r3) : "r"(addr));
}
__device__ __forceinline__ void mma16816(float* d, uint32_t a0, uint32_t a1, uint32_t a2, uint32_t a3,
                                         uint32_t b0, uint32_t b1)
{
    asm volatile("mma.sync.aligned.m16n8k16.row.col.f32.f16.f16.f32 "
                 "{%0,%1,%2,%3}, {%4,%5,%6,%7}, {%8,%9}, {%0,%1,%2,%3};"
                 : "+f"(d[0]), "+f"(d[1]), "+f"(d[2]), "+f"(d[3])
                 : "r"(a0), "r"(a1), "r"(a2), "r"(a3), "r"(b0), "r"(b1));
}

// ---------------------------------------------------------------------------
// Kernel B: fused mask + softmax(no-rescale) + PV matmul + elu
// One CTA = 128 i-rows of one batch. Loop over j in tiles of 64.
// 8 warps, each owns 16 i-rows x 64 outs (8 n8 tiles) + rowsum via ones-column.
// ---------------------------------------------------------------------------
__global__ __launch_bounds__(256, 3) void k_attn(const int* __restrict__ adj,
                                                 float* __restrict__ out)
{
    __shared__ __align__(16) __half p_sm[BI * PPITCH];   // 18 KB
    __shared__ __align__(16) __half h_sm[BJ * HPITCH];   // 9 KB

    const int tid  = threadIdx.x;
    const int lane = tid & 31;
    const int warp = tid >> 5;
    const int blk  = blockIdx.x;        // 0..255
    const int b    = blk >> 5;
    const int i0   = (blk & 31) * BI;

    float acc[8][4];
    float rs[4];
#pragma unroll
    for (int t = 0; t < 8; t++)
#pragma unroll
        for (int k = 0; k < 4; k++) acc[t][k] = 0.f;
#pragma unroll
    for (int k = 0; k < 4; k++) rs[k] = 0.f;

    // ones-column B fragment: B[k][0]=1 for all k -> lanes 0..3 hold 1.0h pairs
    const uint32_t ones = (lane < 4) ? 0x3C003C00u : 0u;

    const int cx = tid & 15;   // 4 j-columns per thread
    const int ry = tid >> 4;   // row within a 16-row pass

    const uint32_t p_base = (uint32_t)__cvta_generic_to_shared(p_sm);
    const uint32_t h_base = (uint32_t)__cvta_generic_to_shared(h_sm);
    const uint32_t a_addr0 = p_base + (uint32_t)(((warp * 16 + (lane & 15)) * PPITCH + (lane >> 4) * 8) * 2);
    const uint32_t b_addr0 = h_base + (uint32_t)((((lane & 15)) * HPITCH + (lane >> 4) * 8) * 2);

    const float2* pq1b = pq1_g + b * NN + i0;
    const float2* pq2b = pq2_g + b * NN;
    const __half* hgb  = h_fp16 + (size_t)b * NN * FO;
    const int*    adjb = adj + (size_t)(b * NN + i0) * NN + cx * 4;

    for (int j0 = 0; j0 < NN; j0 += BJ) {
        // per-thread P2/Q2 for its 4 fixed j-columns of this tile
        float4 pa = *(const float4*)(pq2b + j0 + cx * 4);       // {P2_0,Q2_0,P2_1,Q2_1}
        float4 pb = *(const float4*)(pq2b + j0 + cx * 4 + 2);   // {P2_2,Q2_2,P2_3,Q2_3}

        __syncthreads();   // previous tile's ldmatrix reads are done

        // ---- compute p tile (128 x 64) -> SMEM fp16 ----
#pragma unroll 4
        for (int ps = 0; ps < 8; ps++) {
            int row = ps * 16 + ry;
            int4 av = __ldcs((const int4*)(adjb + (size_t)row * NN + j0));
            float2 pq1 = pq1b[row];
            float p0 = av.x ? fmaxf(pq1.x * pa.x, pq1.y * pa.y) : 0.f;
            float p1 = av.y ? fmaxf(pq1.x * pa.z, pq1.y * pa.w) : 0.f;
            float p2 = av.z ? fmaxf(pq1.x * pb.x, pq1.y * pb.y) : 0.f;
            float p3 = av.w ? fmaxf(pq1.x * pb.z, pq1.y * pb.w) : 0.f;
            __half2 q01 = __floats2half2_rn(p0, p1);
            __half2 q23 = __floats2half2_rn(p2, p3);
            uint2 pk;
            pk.x = reinterpret_cast<uint32_t&>(q01);
            pk.y = reinterpret_cast<uint32_t&>(q23);
            *reinterpret_cast<uint2*>(&p_sm[row * PPITCH + cx * 4]) = pk;
        }

        // ---- load h tile (64 x 64 fp16) -> SMEM ----
#pragma unroll
        for (int c = 0; c < 2; c++) {
            int chunk = tid + c * 256;     // 512 chunks of 16B
            int hrow  = chunk >> 3;
            int seg   = chunk & 7;
            uint4 v = __ldg((const uint4*)(hgb + (size_t)(j0 + hrow) * FO + seg * 8));
            *reinterpret_cast<uint4*>(&h_sm[hrow * HPITCH + seg * 8]) = v;
        }

        __syncthreads();

        // ---- MMA: acc += p @ h, rs += p @ ones ----
#pragma unroll
        for (int ks = 0; ks < 4; ks++) {
            uint32_t a0, a1, a2, a3;
            ldsm4(a0, a1, a2, a3, a_addr0 + ks * 32);
#pragma unroll
            for (int nt = 0; nt < 4; nt++) {
                uint32_t b0, b1, b2, b3;
                ldsm4t(b0, b1, b2, b3, b_addr0 + (uint32_t)((ks * 16 * HPITCH + nt * 16) * 2));
                mma16816(acc[nt * 2],     a0, a1, a2, a3, b0, b1);
                mma16816(acc[nt * 2 + 1], a0, a1, a2, a3, b2, b3);
            }
            mma16816(rs, a0, a1, a2, a3, ones, ones);
        }
    }

    // ---- epilogue: divide by rowsum, elu, store ----
    float rlo = __shfl_sync(0xffffffffu, rs[0], lane & ~3);
    float rhi = __shfl_sync(0xffffffffu, rs[2], lane & ~3);
    float ilo = 1.f / rlo;
    float ihi = 1.f / rhi;

    const int r_lo = i0 + warp * 16 + (lane >> 2);
    float* ob = out + (size_t)b * NN * FO;
#pragma unroll
    for (int nt = 0; nt < 8; nt++) {
        int col = nt * 8 + (lane & 3) * 2;
        float v0 = acc[nt][0] * ilo;
        float v1 = acc[nt][1] * ilo;
        float v2 = acc[nt][2] * ihi;
        float v3 = acc[nt][3] * ihi;
        v0 = v0 > 0.f ? v0 : expm1f(v0);
        v1 = v1 > 0.f ? v1 : expm1f(v1);
        v2 = v2 > 0.f ? v2 : expm1f(v2);
        v3 = v3 > 0.f ? v3 : expm1f(v3);
        *reinterpret_cast<float2*>(&ob[(size_t)r_lo * FO + col])       = make_float2(v0, v1);
        *reinterpret_cast<float2*>(&ob[(size_t)(r_lo + 8) * FO + col]) = make_float2(v2, v3);
    }
}

// ---------------------------------------------------------------------------
extern "C" void kernel_launch(void* const* d_in, const int* in_sizes, int n_in,
                              void* d_out, int out_size)
{
    const float* inp = (const float*)d_in[0];
    const int*   adj = (const int*)d_in[1];
    const float* W   = (const float*)d_in[2];
    const float* a   = (const float*)d_in[3];
    float* out = (float*)d_out;

    k_h<<<BB * NN / 16, 256>>>(inp, W, a);
    k_pq<<<BB, 512>>>();
    k_attn<<<BB * (NN / BI), 256>>>(adj, out);
}

// round 2
// speedup vs baseline: 1.6094x; 1.6094x over previous
#include <cuda_runtime.h>
#include <cuda_fp16.h>
#include <cstdint>

#define BB 8
#define NN 4096
#define FI 128
#define FO 64
#define BI 64
#define BJ 64
#define NT (NN / BJ)
#define PPITCH 72
#define HPITCH 72

// Scratch (static __device__ — no allocation allowed)
__device__ __half h_fp16[(size_t)BB * NN * FO];   // 4 MB
__device__ float  s1_g[BB * NN];
__device__ float  s2_g[BB * NN];
__device__ float2 pq1_g[BB * NN];                 // {P1, Q1} per (b,i)
__device__ float2 pq2_g[BB * NN];                 // {P2, Q2} per (b,j)

// ---------------------------------------------------------------------------
// Kernel A1: h = inp @ W (fp32, fp16 store), s1 = h@a1, s2 = h@a2
// 64 rows per CTA, 256 threads. Thread (rg=tid>>4, ox=tid&15) computes
// 4 rows {rg, rg+16, rg+32, rg+48} x 4 cols {ox*4..ox*4+3}:
// per f: 1 LDS.128 (W) + 4 broadcast LDS.32 (inp) feed 16 FMAs.
// ---------------------------------------------------------------------------
#define KH_IPITCH 132
#define KH_SMEM ((FI * FO + 64 * KH_IPITCH + 2 * FO) * 4)

__global__ __launch_bounds__(256) void k_h(const float* __restrict__ inp,
                                           const float* __restrict__ W,
                                           const float* __restrict__ a)
{
    extern __shared__ float sm_f[];
    float* W_sm   = sm_f;                       // 128*64
    float* inp_sm = sm_f + FI * FO;             // 64*132
    float* a_sm   = inp_sm + 64 * KH_IPITCH;    // 128

    const int tid = threadIdx.x;
    const int blk = blockIdx.x;                 // 0 .. BB*NN/64-1
    const int b   = blk / (NN / 64);
    const int i0  = (blk % (NN / 64)) * 64;

#pragma unroll
    for (int k = 0; k < 8; k++)
        ((float4*)W_sm)[tid + k * 256] = ((const float4*)W)[tid + k * 256];
    if (tid < 2 * FO) a_sm[tid] = a[tid];
    const float* inp_b = inp + ((size_t)b * NN + i0) * FI;
#pragma unroll
    for (int k = 0; k < 8; k++) {
        int c = tid + k * 256;              // float4 index over 64x128
        int row = c >> 5, col = c & 31;
        *(float4*)(inp_sm + row * KH_IPITCH + col * 4) = ((const float4*)inp_b)[c];
    }
    __syncthreads();

    const int ox = tid & 15;
    const int rg = tid >> 4;
    const float4* Wv = (const float4*)W_sm;

    float4 acc[4];
#pragma unroll
    for (int k = 0; k < 4; k++) acc[k] = make_float4(0.f, 0.f, 0.f, 0.f);

#pragma unroll 4
    for (int f = 0; f < FI; f++) {
        float4 w = Wv[f * 16 + ox];
#pragma unroll
        for (int k = 0; k < 4; k++) {
            float x = inp_sm[(rg + 16 * k) * KH_IPITCH + f];
            acc[k].x += x * w.x; acc[k].y += x * w.y;
            acc[k].z += x * w.z; acc[k].w += x * w.w;
        }
    }

    const int o4 = ox * 4;
#pragma unroll
    for (int k = 0; k < 4; k++) {
        float s1p = acc[k].x * a_sm[o4] + acc[k].y * a_sm[o4 + 1]
                  + acc[k].z * a_sm[o4 + 2] + acc[k].w * a_sm[o4 + 3];
        float s2p = acc[k].x * a_sm[FO + o4] + acc[k].y * a_sm[FO + o4 + 1]
                  + acc[k].z * a_sm[FO + o4 + 2] + acc[k].w * a_sm[FO + o4 + 3];
#pragma unroll
        for (int m = 8; m >= 1; m >>= 1) {
            s1p += __shfl_xor_sync(0xffffffffu, s1p, m);
            s2p += __shfl_xor_sync(0xffffffffu, s2p, m);
        }
        const int grow = b * NN + i0 + rg + 16 * k;
        if (ox == 0) { s1_g[grow] = s1p; s2_g[grow] = s2p; }

        __half2 h01 = __floats2half2_rn(acc[k].x, acc[k].y);
        __half2 h23 = __floats2half2_rn(acc[k].z, acc[k].w);
        __half2* dst = (__half2*)(h_fp16 + (size_t)grow * FO + o4);
        dst[0] = h01; dst[1] = h23;
    }
}

// ---------------------------------------------------------------------------
// Kernel A2: per-b s2max reduction, then
//   M_i  = lrelu(s1L_i + s2maxL)           (L = log2 e)
//   P1_i = 2^(s1L_i - M_i),  Q1_i = 2^(0.2*s1L_i - M_i)
//   P2_j = 2^(s2L_j),        Q2_j = 2^(0.2*s2L_j)
// so that  exp(lrelu(s1+s2) - M/L) = max(P1*P2, Q1*Q2)
// ---------------------------------------------------------------------------
__global__ void k_pq()
{
    const int b = blockIdx.x;
    const int tid = threadIdx.x;      // 512 threads
    __shared__ float red[16];

    const float* s2b = s2_g + b * NN;
    float mx = -1e30f;
    for (int j = tid; j < NN; j += 512) mx = fmaxf(mx, s2b[j]);
#pragma unroll
    for (int m = 16; m >= 1; m >>= 1)
        mx = fmaxf(mx, __shfl_xor_sync(0xffffffffu, mx, m));
    if ((tid & 31) == 0) red[tid >> 5] = mx;
    __syncthreads();
    if (tid == 0) {
        float v = red[0];
        for (int k = 1; k < 16; k++) v = fmaxf(v, red[k]);
        red[0] = v;
    }
    __syncthreads();

    const float L = 1.4426950408889634f;
    const float s2maxL = red[0] * L;
    for (int j = tid; j < NN; j += 512) {
        float sL = s2b[j] * L;
        pq2_g[b * NN + j] = make_float2(exp2f(sL), exp2f(0.2f * sL));
        float s1L = s1_g[b * NN + j] * L;
        float t = s1L + s2maxL;
        float M = fmaxf(t, 0.2f * t);
        pq1_g[b * NN + j] = make_float2(exp2f(s1L - M), exp2f(0.2f * s1L - M));
    }
}

// ---------------------------------------------------------------------------
// mma / ldmatrix / cp.async helpers
// ---------------------------------------------------------------------------
__device__ __forceinline__ void ldsm4(uint32_t& r0, uint32_t& r1, uint32_t& r2, uint32_t& r3, uint32_t addr)
{
    asm volatile("ldmatrix.sync.aligned.m8n8.x4.shared.b16 {%0,%1,%2,%3}, [%4];"
                 : "=r"(r0), "=r"(r1), "=r"(r2), "=r"(r3) : "r"(addr));
}
__device__ __forceinline__ void ldsm4t(uint32_t& r0, uint32_t& r1, uint32_t& r2, uint32_t& r3, uint32_t addr)
{
    asm volatile("ldmatrix.sync.aligned.m8n8.x4.trans.shared.b16 {%0,%1,%2,%3}, [%4];"
                 : "=r"(r0), "=r"(r1), "=r"(r2), "=r"(r3) : "r"(addr));
}
__device__ __forceinline__ void mma16816(float* d, uint32_t a0, uint32_t a1, uint32_t a2, uint32_t a3,
                                         uint32_t b0, uint32_t b1)
{
    asm volatile("mma.sync.aligned.m16n8k16.row.col.f32.f16.f16.f32 "
                 "{%0,%1,%2,%3}, {%4,%5,%6,%7}, {%8,%9}, {%0,%1,%2,%3};"
                 : "+f"(d[0]), "+f"(d[1]), "+f"(d[2]), "+f"(d[3])
                 : "r"(a0), "r"(a1), "r"(a2), "r"(a3), "r"(b0), "r"(b1));
}
__device__ __forceinline__ void cpa16(uint32_t smem, const void* g)
{
    asm volatile("cp.async.cg.shared.global [%0], [%1], 16;" :: "r"(smem), "l"(g));
}
__device__ __forceinline__ void cpa_commit() { asm volatile("cp.async.commit_group;"); }
__device__ __forceinline__ void cpa_wait1()  { asm volatile("cp.async.wait_group 1;"); }

// ---------------------------------------------------------------------------
// Kernel B: fused mask + softmax(no-rescale) + PV matmul + elu.
// One CTA = 64 i-rows of one batch (512 CTAs). 128 threads, 4 warps; warp w
// owns i-rows [w*16, w*16+16) x all 64 outs + rowsum via ones-column mma.
// Pipeline: adj tile t+1 prefetched into registers (LDG.128), h tile t+1 via
// cp.async into double-buffered SMEM; p tile double-buffered; 2 bars/iter.
// ---------------------------------------------------------------------------
__global__ __launch_bounds__(128, 3) void k_attn(const int* __restrict__ adj,
                                                 float* __restrict__ out)
{
    __shared__ __align__(16) __half p_sm[2 * BI * PPITCH];   // 18 KB
    __shared__ __align__(16) __half h_sm[2 * BJ * HPITCH];   // 18 KB

    const int tid  = threadIdx.x;
    const int lane = tid & 31;
    const int warp = tid >> 5;
    const int blk  = blockIdx.x;        // 0..511
    const int b    = blk >> 6;
    const int i0   = (blk & 63) * BI;

    float acc[8][4];
    float rs[4];
#pragma unroll
    for (int t = 0; t < 8; t++)
#pragma unroll
        for (int k = 0; k < 4; k++) acc[t][k] = 0.f;
#pragma unroll
    for (int k = 0; k < 4; k++) rs[k] = 0.f;

    // ones-column B fragment: B[k][0]=1 for all k
    const uint32_t ones = (lane < 4) ? 0x3C003C00u : 0u;

    const int cx = tid & 15;   // 4 j-columns per thread
    const int ry = tid >> 4;   // 0..7

    const uint32_t p_base = (uint32_t)__cvta_generic_to_shared(p_sm);
    const uint32_t h_base = (uint32_t)__cvta_generic_to_shared(h_sm);
    const uint32_t PBUF = BI * PPITCH * 2;   // bytes per p buffer
    const uint32_t HBUF = BJ * HPITCH * 2;   // bytes per h buffer
    const uint32_t a_off = (uint32_t)(((warp * 16 + (lane & 15)) * PPITCH + (lane >> 4) * 8) * 2);
    const uint32_t b_off = (uint32_t)(((lane & 15) * HPITCH + (lane >> 4) * 8) * 2);

    const float2* pq1b = pq1_g + b * NN + i0;
    const float2* pq2b = pq2_g + b * NN;
    const __half* hgb  = h_fp16 + (size_t)b * NN * FO;
    const int*    adjb = adj + (size_t)(b * NN + i0) * NN + cx * 4;

    // h-tile cp.async chunk coords (4 chunks/thread, 16B each)
    const int hrow0 = tid >> 3;        // chunk c = tid + k*128 -> row c>>3
    const int hseg  = (tid & 7) * 8;   // halves

    // ---- prolog: h tile 0 + adj tile 0 ----
#pragma unroll
    for (int k = 0; k < 4; k++) {
        int hrow = hrow0 + k * 16;
        cpa16(h_base + (uint32_t)((hrow * HPITCH + hseg) * 2),
              hgb + (size_t)hrow * FO + hseg);
    }
    cpa_commit();

    int4 A[8];
#pragma unroll
    for (int ps = 0; ps < 8; ps++)
        A[ps] = *(const int4*)(adjb + (size_t)(ps * 8 + ry) * NN);

    for (int t = 0; t < NT; ++t) {
        const int cur = t & 1, nxt = cur ^ 1;
        const int j0 = t * BJ;

        // prefetch adj tile t+1 into registers
        int4 An[8];
        if (t < NT - 1) {
#pragma unroll
            for (int ps = 0; ps < 8; ps++)
                An[ps] = *(const int4*)(adjb + (size_t)(ps * 8 + ry) * NN + j0 + BJ);
        }
        // prefetch h tile t+1 into h_sm[nxt]
        if (t < NT - 1) {
#pragma unroll
            for (int k = 0; k < 4; k++) {
                int hrow = hrow0 + k * 16;
                cpa16(h_base + nxt * HBUF + (uint32_t)((hrow * HPITCH + hseg) * 2),
                      hgb + (size_t)(j0 + BJ + hrow) * FO + hseg);
            }
        }
        cpa_commit();

        // ---- compute p tile (64 x 64) -> p_sm[cur] ----
        float4 pa = *(const float4*)(pq2b + j0 + cx * 4);
        float4 pb = *(const float4*)(pq2b + j0 + cx * 4 + 2);
#pragma unroll
        for (int ps = 0; ps < 8; ps++) {
            int row = ps * 8 + ry;
            float2 pq1 = __ldg(&pq1b[row]);
            int4 av = A[ps];
            float p0 = av.x ? fmaxf(pq1.x * pa.x, pq1.y * pa.y) : 0.f;
            float p1 = av.y ? fmaxf(pq1.x * pa.z, pq1.y * pa.w) : 0.f;
            float p2 = av.z ? fmaxf(pq1.x * pb.x, pq1.y * pb.y) : 0.f;
            float p3 = av.w ? fmaxf(pq1.x * pb.z, pq1.y * pb.w) : 0.f;
            __half2 q01 = __floats2half2_rn(p0, p1);
            __half2 q23 = __floats2half2_rn(p2, p3);
            uint2 pk;
            pk.x = reinterpret_cast<uint32_t&>(q01);
            pk.y = reinterpret_cast<uint32_t&>(q23);
            *reinterpret_cast<uint2*>(&p_sm[cur * BI * PPITCH + row * PPITCH + cx * 4]) = pk;
        }

        cpa_wait1();          // h tile t resident
        __syncthreads();      // p_sm[cur] + h_sm[cur] visible to all

        // ---- MMA: acc += p @ h, rs += p @ ones ----
        const uint32_t a_addr = p_base + cur * PBUF + a_off;
        const uint32_t b_addr = h_base + cur * HBUF + b_off;
#pragma unroll
        for (int ks = 0; ks < 4; ks++) {
            uint32_t a0, a1, a2, a3;
            ldsm4(a0, a1, a2, a3, a_addr + ks * 32);
#pragma unroll
            for (int nt2 = 0; nt2 < 4; nt2++) {
                uint32_t b0, b1, b2, b3;
                ldsm4t(b0, b1, b2, b3, b_addr + (uint32_t)((ks * 16 * HPITCH + nt2 * 16) * 2));
                mma16816(acc[nt2 * 2],     a0, a1, a2, a3, b0, b1);
                mma16816(acc[nt2 * 2 + 1], a0, a1, a2, a3, b2, b3);
            }
            mma16816(rs, a0, a1, a2, a3, ones, ones);
        }
        __syncthreads();      // all reads of cur buffers done before reuse

#pragma unroll
        for (int ps = 0; ps < 8; ps++) A[ps] = An[ps];
    }

    // ---- epilogue: divide by rowsum, elu, store ----
    float rlo = __shfl_sync(0xffffffffu, rs[0], lane & ~3);
    float rhi = __shfl_sync(0xffffffffu, rs[2], lane & ~3);
    float ilo = 1.f / rlo;
    float ihi = 1.f / rhi;

    const int r_lo = i0 + warp * 16 + (lane >> 2);
    float* ob = out + (size_t)b * NN * FO;
#pragma unroll
    for (int nt2 = 0; nt2 < 8; nt2++) {
        int col = nt2 * 8 + (lane & 3) * 2;
        float v0 = acc[nt2][0] * ilo;
        float v1 = acc[nt2][1] * ilo;
        float v2 = acc[nt2][2] * ihi;
        float v3 = acc[nt2][3] * ihi;
        v0 = v0 > 0.f ? v0 : expm1f(v0);
        v1 = v1 > 0.f ? v1 : expm1f(v1);
        v2 = v2 > 0.f ? v2 : expm1f(v2);
        v3 = v3 > 0.f ? v3 : expm1f(v3);
        *reinterpret_cast<float2*>(&ob[(size_t)r_lo * FO + col])       = make_float2(v0, v1);
        *reinterpret_cast<float2*>(&ob[(size_t)(r_lo + 8) * FO + col]) = make_float2(v2, v3);
    }
}

// ---------------------------------------------------------------------------
extern "C" void kernel_launch(void* const* d_in, const int* in_sizes, int n_in,
                              void* d_out, int out_size)
{
    const float* inp = (const float*)d_in[0];
    const int*   adj = (const int*)d_in[1];
    const float* W   = (const float*)d_in[2];
    const float* a   = (const float*)d_in[3];
    float* out = (float*)d_out;

    static bool attr_set = false;
    if (!attr_set) {
        cudaFuncSetAttribute(k_h, cudaFuncAttributeMaxDynamicSharedMemorySize, KH_SMEM);
        attr_set = true;
    }

    k_h<<<BB * NN / 64, 256, KH_SMEM>>>(inp, W, a);
    k_pq<<<BB, 512>>>();
    k_attn<<<BB * (NN / BI), 128>>>(adj, out);
}

// round 3
// speedup vs baseline: 1.6143x; 1.0030x over previous
#include <cuda_runtime.h>
#include <cuda_fp16.h>
#include <cstdint>

#define BB 8
#define NN 4096
#define FI 128
#define FO 64
#define BI 64
#define BJ 64
#define NT (NN / BJ)
#define PPITCH 72
#define HPITCH 72

// Scratch (static __device__ — no allocation allowed)
__device__ __half h_fp16[(size_t)BB * NN * FO];   // 4 MB
__device__ float  s1_g[BB * NN];
__device__ float  s2_g[BB * NN];
__device__ float2 pq1_g[BB * NN];                 // {P1, Q1} per (b,i)
__device__ float2 pq2_g[BB * NN];                 // {P2, Q2} per (b,j)

// ---------------------------------------------------------------------------
// Kernel A1: h = inp @ W (fp32, fp16 store), s1 = h@a1, s2 = h@a2
// 64 rows per CTA, 256 threads. Thread (rg=tid>>4, ox=tid&15) computes
// 4 rows {rg, rg+16, rg+32, rg+48} x 4 cols {ox*4..ox*4+3}:
// per f: 1 LDS.128 (W) + 4 broadcast LDS.32 (inp) feed 16 FMAs.
// ---------------------------------------------------------------------------
#define KH_IPITCH 132
#define KH_SMEM ((FI * FO + 64 * KH_IPITCH + 2 * FO) * 4)

__global__ __launch_bounds__(256) void k_h(const float* __restrict__ inp,
                                           const float* __restrict__ W,
                                           const float* __restrict__ a)
{
    extern __shared__ float sm_f[];
    float* W_sm   = sm_f;                       // 128*64
    float* inp_sm = sm_f + FI * FO;             // 64*132
    float* a_sm   = inp_sm + 64 * KH_IPITCH;    // 128

    const int tid = threadIdx.x;
    const int blk = blockIdx.x;                 // 0 .. BB*NN/64-1
    const int b   = blk / (NN / 64);
    const int i0  = (blk % (NN / 64)) * 64;

#pragma unroll
    for (int k = 0; k < 8; k++)
        ((float4*)W_sm)[tid + k * 256] = ((const float4*)W)[tid + k * 256];
    if (tid < 2 * FO) a_sm[tid] = a[tid];
    const float* inp_b = inp + ((size_t)b * NN + i0) * FI;
#pragma unroll
    for (int k = 0; k < 8; k++) {
        int c = tid + k * 256;              // float4 index over 64x128
        int row = c >> 5, col = c & 31;
        *(float4*)(inp_sm + row * KH_IPITCH + col * 4) = ((const float4*)inp_b)[c];
    }
    __syncthreads();

    const int ox = tid & 15;
    const int rg = tid >> 4;
    const float4* Wv = (const float4*)W_sm;

    float4 acc[4];
#pragma unroll
    for (int k = 0; k < 4; k++) acc[k] = make_float4(0.f, 0.f, 0.f, 0.f);

#pragma unroll 4
    for (int f = 0; f < FI; f++) {
        float4 w = Wv[f * 16 + ox];
#pragma unroll
        for (int k = 0; k < 4; k++) {
            float x = inp_sm[(rg + 16 * k) * KH_IPITCH + f];
            acc[k].x += x * w.x; acc[k].y += x * w.y;
            acc[k].z += x * w.z; acc[k].w += x * w.w;
        }
    }

    const int o4 = ox * 4;
#pragma unroll
    for (int k = 0; k < 4; k++) {
        float s1p = acc[k].x * a_sm[o4] + acc[k].y * a_sm[o4 + 1]
                  + acc[k].z * a_sm[o4 + 2] + acc[k].w * a_sm[o4 + 3];
        float s2p = acc[k].x * a_sm[FO + o4] + acc[k].y * a_sm[FO + o4 + 1]
                  + acc[k].z * a_sm[FO + o4 + 2] + acc[k].w * a_sm[FO + o4 + 3];
#pragma unroll
        for (int m = 8; m >= 1; m >>= 1) {
            s1p += __shfl_xor_sync(0xffffffffu, s1p, m);
            s2p += __shfl_xor_sync(0xffffffffu, s2p, m);
        }
        const int grow = b * NN + i0 + rg + 16 * k;
        if (ox == 0) { s1_g[grow] = s1p; s2_g[grow] = s2p; }

        __half2 h01 = __floats2half2_rn(acc[k].x, acc[k].y);
        __half2 h23 = __floats2half2_rn(acc[k].z, acc[k].w);
        __half2* dst = (__half2*)(h_fp16 + (size_t)grow * FO + o4);
        dst[0] = h01; dst[1] = h23;
    }
}

// ---------------------------------------------------------------------------
// Kernel A2: per-b s2max reduction, then
//   M_i  = lrelu(s1L_i + s2maxL)           (L = log2 e)
//   P1_i = 2^(s1L_i - M_i),  Q1_i = 2^(0.2*s1L_i - M_i)
//   P2_j = 2^(s2L_j),        Q2_j = 2^(0.2*s2L_j)
// so that  exp(lrelu(s1+s2) - M/L) = max(P1*P2, Q1*Q2)
// ---------------------------------------------------------------------------
__global__ void k_pq()
{
    const int b = blockIdx.x;
    const int tid = threadIdx.x;      // 512 threads
    __shared__ float red[16];

    const float* s2b = s2_g + b * NN;
    float mx = -1e30f;
    for (int j = tid; j < NN; j += 512) mx = fmaxf(mx, s2b[j]);
#pragma unroll
    for (int m = 16; m >= 1; m >>= 1)
        mx = fmaxf(mx, __shfl_xor_sync(0xffffffffu, mx, m));
    if ((tid & 31) == 0) red[tid >> 5] = mx;
    __syncthreads();
    if (tid == 0) {
        float v = red[0];
        for (int k = 1; k < 16; k++) v = fmaxf(v, red[k]);
        red[0] = v;
    }
    __syncthreads();

    const float L = 1.4426950408889634f;
    const float s2maxL = red[0] * L;
    for (int j = tid; j < NN; j += 512) {
        float sL = s2b[j] * L;
        pq2_g[b * NN + j] = make_float2(exp2f(sL), exp2f(0.2f * sL));
        float s1L = s1_g[b * NN + j] * L;
        float t = s1L + s2maxL;
        float M = fmaxf(t, 0.2f * t);
        pq1_g[b * NN + j] = make_float2(exp2f(s1L - M), exp2f(0.2f * s1L - M));
    }
}

// ---------------------------------------------------------------------------
// mma / ldmatrix / cp.async helpers
// ---------------------------------------------------------------------------
__device__ __forceinline__ void ldsm4(uint32_t& r0, uint32_t& r1, uint32_t& r2, uint32_t& r3, uint32_t addr)
{
    asm volatile("ldmatrix.sync.aligned.m8n8.x4.shared.b16 {%0,%1,%2,%3}, [%4];"
                 : "=r"(r0), "=r"(r1), "=r"(r2), "=r"(r3) : "r"(addr));
}
__device__ __forceinline__ void ldsm4t(uint32_t& r0, uint32_t& r1, uint32_t& r2, uint32_t& r3, uint32_t addr)
{
    asm volatile("ldmatrix.sync.aligned.m8n8.x4.trans.shared.b16 {%0,%1,%2,%3}, [%4];"
                 : "=r"(r0), "=r"(r1), "=r"(r2), "=r"(r3) : "r"(addr));
}
__device__ __forceinline__ void mma16816(float* d, uint32_t a0, uint32_t a1, uint32_t a2, uint32_t a3,
                                         uint32_t b0, uint32_t b1)
{
    asm volatile("mma.sync.aligned.m16n8k16.row.col.f32.f16.f16.f32 "
                 "{%0,%1,%2,%3}, {%4,%5,%6,%7}, {%8,%9}, {%0,%1,%2,%3};"
                 : "+f"(d[0]), "+f"(d[1]), "+f"(d[2]), "+f"(d[3])
                 : "r"(a0), "r"(a1), "r"(a2), "r"(a3), "r"(b0), "r"(b1));
}
__device__ __forceinline__ void cpa16(uint32_t smem, const void* g)
{
    asm volatile("cp.async.cg.shared.global [%0], [%1], 16;" :: "r"(smem), "l"(g));
}
__device__ __forceinline__ void cpa_commit() { asm volatile("cp.async.commit_group;"); }
__device__ __forceinline__ void cpa_wait1()  { asm volatile("cp.async.wait_group 1;"); }

// ---------------------------------------------------------------------------
// Kernel B: fused mask + softmax(no-rescale) + PV matmul + elu.
// One CTA = 64 i-rows of one batch (512 CTAs). 128 threads, 4 warps; warp w
// owns i-rows [w*16, w*16+16) x all 64 outs + rowsum via ones-column mma.
// Pipeline: adj tile t+1 prefetched into registers (LDG.128), h tile t+1 via
// cp.async into double-buffered SMEM; p tile double-buffered; 2 bars/iter.
// ---------------------------------------------------------------------------
__global__ __launch_bounds__(128, 3) void k_attn(const int* __restrict__ adj,
                                                 float* __restrict__ out)
{
    __shared__ __align__(16) __half p_sm[2 * BI * PPITCH];   // 18 KB
    __shared__ __align__(16) __half h_sm[2 * BJ * HPITCH];   // 18 KB

    const int tid  = threadIdx.x;
    const int lane = tid & 31;
    const int warp = tid >> 5;
    const int blk  = blockIdx.x;        // 0..511
    const int b    = blk >> 6;
    const int i0   = (blk & 63) * BI;

    float acc[8][4];
    float rs[4];
#pragma unroll
    for (int t = 0; t < 8; t++)
#pragma unroll
        for (int k = 0; k < 4; k++) acc[t][k] = 0.f;
#pragma unroll
    for (int k = 0; k < 4; k++) rs[k] = 0.f;

    // ones-column B fragment: B[k][0]=1 for all k
    const uint32_t ones = (lane < 4) ? 0x3C003C00u : 0u;

    const int cx = tid & 15;   // 4 j-columns per thread
    const int ry = tid >> 4;   // 0..7

    const uint32_t p_base = (uint32_t)__cvta_generic_to_shared(p_sm);
    const uint32_t h_base = (uint32_t)__cvta_generic_to_shared(h_sm);
    const uint32_t PBUF = BI * PPITCH * 2;   // bytes per p buffer
    const uint32_t HBUF = BJ * HPITCH * 2;   // bytes per h buffer
    const uint32_t a_off = (uint32_t)(((warp * 16 + (lane & 15)) * PPITCH + (lane >> 4) * 8) * 2);
    const uint32_t b_off = (uint32_t)(((lane & 15) * HPITCH + (lane >> 4) * 8) * 2);

    const float2* pq1b = pq1_g + b * NN + i0;
    const float2* pq2b = pq2_g + b * NN;
    const __half* hgb  = h_fp16 + (size_t)b * NN * FO;
    const int*    adjb = adj + (size_t)(b * NN + i0) * NN + cx * 4;

    // h-tile cp.async chunk coords (4 chunks/thread, 16B each)
    const int hrow0 = tid >> 3;        // chunk c = tid + k*128 -> row c>>3
    const int hseg  = (tid & 7) * 8;   // halves

    // ---- prolog: h tile 0 + adj tile 0 ----
#pragma unroll
    for (int k = 0; k < 4; k++) {
        int hrow = hrow0 + k * 16;
        cpa16(h_base + (uint32_t)((hrow * HPITCH + hseg) * 2),
              hgb + (size_t)hrow * FO + hseg);
    }
    cpa_commit();

    int4 A[8];
#pragma unroll
    for (int ps = 0; ps < 8; ps++)
        A[ps] = *(const int4*)(adjb + (size_t)(ps * 8 + ry) * NN);

    for (int t = 0; t < NT; ++t) {
        const int cur = t & 1, nxt = cur ^ 1;
        const int j0 = t * BJ;

        // prefetch adj tile t+1 into registers
        int4 An[8];
        if (t < NT - 1) {
#pragma unroll
            for (int ps = 0; ps < 8; ps++)
                An[ps] = *(const int4*)(adjb + (size_t)(ps * 8 + ry) * NN + j0 + BJ);
        }
        // prefetch h tile t+1 into h_sm[nxt]
        if (t < NT - 1) {
#pragma unroll
            for (int k = 0; k < 4; k++) {
                int hrow = hrow0 + k * 16;
                cpa16(h_base + nxt * HBUF + (uint32_t)((hrow * HPITCH + hseg) * 2),
                      hgb + (size_t)(j0 + BJ + hrow) * FO + hseg);
            }
        }
        cpa_commit();

        // ---- compute p tile (64 x 64) -> p_sm[cur] ----
        float4 pa = *(const float4*)(pq2b + j0 + cx * 4);
        float4 pb = *(const float4*)(pq2b + j0 + cx * 4 + 2);
#pragma unroll
        for (int ps = 0; ps < 8; ps++) {
            int row = ps * 8 + ry;
            float2 pq1 = __ldg(&pq1b[row]);
            int4 av = A[ps];
            float p0 = av.x ? fmaxf(pq1.x * pa.x, pq1.y * pa.y) : 0.f;
            float p1 = av.y ? fmaxf(pq1.x * pa.z, pq1.y * pa.w) : 0.f;
            float p2 = av.z ? fmaxf(pq1.x * pb.x, pq1.y * pb.y) : 0.f;
            float p3 = av.w ? fmaxf(pq1.x * pb.z, pq1.y * pb.w) : 0.f;
            __half2 q01 = __floats2half2_rn(p0, p1);
            __half2 q23 = __floats2half2_rn(p2, p3);
            uint2 pk;
            pk.x = reinterpret_cast<uint32_t&>(q01);
            pk.y = reinterpret_cast<uint32_t&>(q23);
            *reinterpret_cast<uint2*>(&p_sm[cur * BI * PPITCH + row * PPITCH + cx * 4]) = pk;
        }

        cpa_wait1();          // h tile t resident
        __syncthreads();      // p_sm[cur] + h_sm[cur] visible to all

        // ---- MMA: acc += p @ h, rs += p @ ones ----
        const uint32_t a_addr = p_base + cur * PBUF + a_off;
        const uint32_t b_addr = h_base + cur * HBUF + b_off;
#pragma unroll
        for (int ks = 0; ks < 4; ks++) {
            uint32_t a0, a1, a2, a3;
            ldsm4(a0, a1, a2, a3, a_addr + ks * 32);
#pragma unroll
            for (int nt2 = 0; nt2 < 4; nt2++) {
                uint32_t b0, b1, b2, b3;
                ldsm4t(b0, b1, b2, b3, b_addr + (uint32_t)((ks * 16 * HPITCH + nt2 * 16) * 2));
                mma16816(acc[nt2 * 2],     a0, a1, a2, a3, b0, b1);
                mma16816(acc[nt2 * 2 + 1], a0, a1, a2, a3, b2, b3);
            }
            mma16816(rs, a0, a1, a2, a3, ones, ones);
        }
        __syncthreads();      // all reads of cur buffers done before reuse

#pragma unroll
        for (int ps = 0; ps < 8; ps++) A[ps] = An[ps];
    }

    // ---- epilogue: divide by rowsum, elu, store ----
    float rlo = __shfl_sync(0xffffffffu, rs[0], lane & ~3);
    float rhi = __shfl_sync(0xffffffffu, rs[2], lane & ~3);
    float ilo = 1.f / rlo;
    float ihi = 1.f / rhi;

    const int r_lo = i0 + warp * 16 + (lane >> 2);
    float* ob = out + (size_t)b * NN * FO;
#pragma unroll
    for (int nt2 = 0; nt2 < 8; nt2++) {
        int col = nt2 * 8 + (lane & 3) * 2;
        float v0 = acc[nt2][0] * ilo;
        float v1 = acc[nt2][1] * ilo;
        float v2 = acc[nt2][2] * ihi;
        float v3 = acc[nt2][3] * ihi;
        v0 = v0 > 0.f ? v0 : expm1f(v0);
        v1 = v1 > 0.f ? v1 : expm1f(v1);
        v2 = v2 > 0.f ? v2 : expm1f(v2);
        v3 = v3 > 0.f ? v3 : expm1f(v3);
        *reinterpret_cast<float2*>(&ob[(size_t)r_lo * FO + col])       = make_float2(v0, v1);
        *reinterpret_cast<float2*>(&ob[(size_t)(r_lo + 8) * FO + col]) = make_float2(v2, v3);
    }
}

// ---------------------------------------------------------------------------
extern "C" void kernel_launch(void* const* d_in, const int* in_sizes, int n_in,
                              void* d_out, int out_size)
{
    const float* inp = (const float*)d_in[0];
    const int*   adj = (const int*)d_in[1];
    const float* W   = (const float*)d_in[2];
    const float* a   = (const float*)d_in[3];
    float* out = (float*)d_out;

    static bool attr_set = false;
    if (!attr_set) {
        cudaFuncSetAttribute(k_h, cudaFuncAttributeMaxDynamicSharedMemorySize, KH_SMEM);
        attr_set = true;
    }

    k_h<<<BB * NN / 64, 256, KH_SMEM>>>(inp, W, a);
    k_pq<<<BB, 512>>>();
    k_attn<<<BB * (NN / BI), 128>>>(adj, out);
}

// round 4
// speedup vs baseline: 1.8906x; 1.1711x over previous
#include <cuda_runtime.h>
#include <cuda_fp16.h>
#include <cstdint>

#define BB 8
#define NN 4096
#define FI 128
#define FO 64
#define BI 64
#define BJ 64
#define NT (NN / BJ)
#define PPITCH 72
#define HPITCH 72

// k_attn shared memory layout (dynamic)
#define APITCH   68                      // ints per adj row
#define ASTAGE_I (64 * APITCH)           // ints per adj stage
#define ASTAGE_B (ASTAGE_I * 4)          // 17408 bytes
#define HBUF_B   (64 * HPITCH * 2)       // 9216 bytes
#define ADJ_OFF  0
#define H_OFF    (3 * ASTAGE_B)          // 52224
#define P_OFF    (H_OFF + 3 * HBUF_B)    // 79872
#define ATTN_SMEM (P_OFF + BI * PPITCH * 2)  // 89088

// Scratch (static __device__ — no allocation allowed)
__device__ __half h_fp16[(size_t)BB * NN * FO];   // 4 MB
__device__ float  s1_g[BB * NN];
__device__ float  s2_g[BB * NN];
__device__ float2 pq1_g[BB * NN];                 // {P1, Q1} per (b,i)
__device__ float2 pq2_g[BB * NN];                 // {P2, Q2} per (b,j)

// ---------------------------------------------------------------------------
// Kernel A1: h = inp @ W (fp32, fp16 store), s1 = h@a1, s2 = h@a2
// ---------------------------------------------------------------------------
#define KH_IPITCH 132
#define KH_SMEM ((FI * FO + 64 * KH_IPITCH + 2 * FO) * 4)

__global__ __launch_bounds__(256) void k_h(const float* __restrict__ inp,
                                           const float* __restrict__ W,
                                           const float* __restrict__ a)
{
    extern __shared__ float sm_f[];
    float* W_sm   = sm_f;                       // 128*64
    float* inp_sm = sm_f + FI * FO;             // 64*132
    float* a_sm   = inp_sm + 64 * KH_IPITCH;    // 128

    const int tid = threadIdx.x;
    const int blk = blockIdx.x;                 // 0 .. BB*NN/64-1
    const int b   = blk / (NN / 64);
    const int i0  = (blk % (NN / 64)) * 64;

#pragma unroll
    for (int k = 0; k < 8; k++)
        ((float4*)W_sm)[tid + k * 256] = ((const float4*)W)[tid + k * 256];
    if (tid < 2 * FO) a_sm[tid] = a[tid];
    const float* inp_b = inp + ((size_t)b * NN + i0) * FI;
#pragma unroll
    for (int k = 0; k < 8; k++) {
        int c = tid + k * 256;
        int row = c >> 5, col = c & 31;
        *(float4*)(inp_sm + row * KH_IPITCH + col * 4) = ((const float4*)inp_b)[c];
    }
    __syncthreads();

    const int ox = tid & 15;
    const int rg = tid >> 4;
    const float4* Wv = (const float4*)W_sm;

    float4 acc[4];
#pragma unroll
    for (int k = 0; k < 4; k++) acc[k] = make_float4(0.f, 0.f, 0.f, 0.f);

#pragma unroll 4
    for (int f = 0; f < FI; f++) {
        float4 w = Wv[f * 16 + ox];
#pragma unroll
        for (int k = 0; k < 4; k++) {
            float x = inp_sm[(rg + 16 * k) * KH_IPITCH + f];
            acc[k].x += x * w.x; acc[k].y += x * w.y;
            acc[k].z += x * w.z; acc[k].w += x * w.w;
        }
    }

    const int o4 = ox * 4;
#pragma unroll
    for (int k = 0; k < 4; k++) {
        float s1p = acc[k].x * a_sm[o4] + acc[k].y * a_sm[o4 + 1]
                  + acc[k].z * a_sm[o4 + 2] + acc[k].w * a_sm[o4 + 3];
        float s2p = acc[k].x * a_sm[FO + o4] + acc[k].y * a_sm[FO + o4 + 1]
                  + acc[k].z * a_sm[FO + o4 + 2] + acc[k].w * a_sm[FO + o4 + 3];
#pragma unroll
        for (int m = 8; m >= 1; m >>= 1) {
            s1p += __shfl_xor_sync(0xffffffffu, s1p, m);
            s2p += __shfl_xor_sync(0xffffffffu, s2p, m);
        }
        const int grow = b * NN + i0 + rg + 16 * k;
        if (ox == 0) { s1_g[grow] = s1p; s2_g[grow] = s2p; }

        __half2 h01 = __floats2half2_rn(acc[k].x, acc[k].y);
        __half2 h23 = __floats2half2_rn(acc[k].z, acc[k].w);
        __half2* dst = (__half2*)(h_fp16 + (size_t)grow * FO + o4);
        dst[0] = h01; dst[1] = h23;
    }
}

// ---------------------------------------------------------------------------
// Kernel A2: exp factor tables.  exp(lrelu(s1+s2) - M/L) = max(P1*P2, Q1*Q2)
// ---------------------------------------------------------------------------
__global__ void k_pq()
{
    const int b = blockIdx.x;
    const int tid = threadIdx.x;      // 512 threads
    __shared__ float red[16];

    const float* s2b = s2_g + b * NN;
    float mx = -1e30f;
    for (int j = tid; j < NN; j += 512) mx = fmaxf(mx, s2b[j]);
#pragma unroll
    for (int m = 16; m >= 1; m >>= 1)
        mx = fmaxf(mx, __shfl_xor_sync(0xffffffffu, mx, m));
    if ((tid & 31) == 0) red[tid >> 5] = mx;
    __syncthreads();
    if (tid == 0) {
        float v = red[0];
        for (int k = 1; k < 16; k++) v = fmaxf(v, red[k]);
        red[0] = v;
    }
    __syncthreads();

    const float L = 1.4426950408889634f;
    const float s2maxL = red[0] * L;
    for (int j = tid; j < NN; j += 512) {
        float sL = s2b[j] * L;
        pq2_g[b * NN + j] = make_float2(exp2f(sL), exp2f(0.2f * sL));
        float s1L = s1_g[b * NN + j] * L;
        float t = s1L + s2maxL;
        float M = fmaxf(t, 0.2f * t);
        pq1_g[b * NN + j] = make_float2(exp2f(s1L - M), exp2f(0.2f * s1L - M));
    }
}

// ---------------------------------------------------------------------------
// PTX helpers
// ---------------------------------------------------------------------------
__device__ __forceinline__ void ldsm4(uint32_t& r0, uint32_t& r1, uint32_t& r2, uint32_t& r3, uint32_t addr)
{
    asm volatile("ldmatrix.sync.aligned.m8n8.x4.shared.b16 {%0,%1,%2,%3}, [%4];"
                 : "=r"(r0), "=r"(r1), "=r"(r2), "=r"(r3) : "r"(addr));
}
__device__ __forceinline__ void ldsm4t(uint32_t& r0, uint32_t& r1, uint32_t& r2, uint32_t& r3, uint32_t addr)
{
    asm volatile("ldmatrix.sync.aligned.m8n8.x4.trans.shared.b16 {%0,%1,%2,%3}, [%4];"
                 : "=r"(r0), "=r"(r1), "=r"(r2), "=r"(r3) : "r"(addr));
}
__device__ __forceinline__ void mma16816(float* d, uint32_t a0, uint32_t a1, uint32_t a2, uint32_t a3,
                                         uint32_t b0, uint32_t b1)
{
    asm volatile("mma.sync.aligned.m16n8k16.row.col.f32.f16.f16.f32 "
                 "{%0,%1,%2,%3}, {%4,%5,%6,%7}, {%8,%9}, {%0,%1,%2,%3};"
                 : "+f"(d[0]), "+f"(d[1]), "+f"(d[2]), "+f"(d[3])
                 : "r"(a0), "r"(a1), "r"(a2), "r"(a3), "r"(b0), "r"(b1));
}
__device__ __forceinline__ void cpa16(uint32_t smem, const void* g)
{
    asm volatile("cp.async.cg.shared.global [%0], [%1], 16;" :: "r"(smem), "l"(g));
}
__device__ __forceinline__ void cpa_commit() { asm volatile("cp.async.commit_group;" ::: "memory"); }
__device__ __forceinline__ void cpa_wait4()  { asm volatile("cp.async.wait_group 4;" ::: "memory"); }

// ---------------------------------------------------------------------------
// Kernel B: fused mask + softmax(no-rescale) + PV matmul + elu.
// 512 CTAs, 128 threads (4 warps). Deep cp.async pipeline:
//  - adj: 3-stage SMEM ring, distance 2, "own-data" (each thread cp.asyncs the
//    exact 16B chunks it consumes -> no barrier needed for adj, wait_group only)
//  - h:   3 buffers, distance 2, shared (visibility via the two barriers)
//  - per iter: commit hG(t+2), commit adjG(t+2), wait_group 4 => hG(t)/adjG(t)
//    complete with 2 iterations of slack; 2 adj tiles always in flight.
// ---------------------------------------------------------------------------
__global__ __launch_bounds__(128, 2) void k_attn(const int* __restrict__ adj,
                                                 float* __restrict__ out)
{
    extern __shared__ __align__(16) unsigned char smem[];
    const uint32_t sb = (uint32_t)__cvta_generic_to_shared(smem);
    int*    adj_sm = (int*)smem;                         // 3 stages
    __half* p_sm   = (__half*)(smem + P_OFF);

    const int tid  = threadIdx.x;
    const int lane = tid & 31;
    const int warp = tid >> 5;
    const int blk  = blockIdx.x;        // 0..511
    const int b    = blk >> 6;
    const int i0   = (blk & 63) * BI;

    const int cx = tid & 15;   // 4 j-columns per thread
    const int ry = tid >> 4;   // 0..7

    float acc[8][4];
    float rs[4];
#pragma unroll
    for (int t = 0; t < 8; t++)
#pragma unroll
        for (int k = 0; k < 4; k++) acc[t][k] = 0.f;
#pragma unroll
    for (int k = 0; k < 4; k++) rs[k] = 0.f;

    const uint32_t ones = (lane < 4) ? 0x3C003C00u : 0u;

    // per-row P1/Q1 (fixed for entire kernel) -> registers
    float P1f[8], Q1f[8];
    {
        const float2* pq1b = pq1_g + b * NN + i0;
#pragma unroll
        for (int ps = 0; ps < 8; ps++) {
            float2 pq = __ldg(&pq1b[ps * 8 + ry]);
            P1f[ps] = pq.x; Q1f[ps] = pq.y;
        }
    }

    const float2* pq2b = pq2_g + b * NN;
    const __half* hgb  = h_fp16 + (size_t)b * NN * FO;
    // adj source base for this thread's chunk rows (row = ps*8 + ry)
    const int* adjb = adj + ((size_t)(b * NN + i0 + ry)) * NN + cx * 4;

    // h cp.async chunk coords (4 chunks/thread, 16B)
    const int hrow0 = tid >> 3;        // 0..15
    const int hseg  = (tid & 7) * 8;   // halves

    // ldmatrix lane addressing
    const uint32_t a_addr = sb + P_OFF + (uint32_t)(((warp * 16 + (lane & 15)) * PPITCH + (lane >> 4) * 8) * 2);
    const uint32_t b_off  = (uint32_t)(((lane & 15) * HPITCH + (lane >> 4) * 8) * 2);

    // -------- issue helpers (inline lambdas) --------
    auto issue_h = [&](int u) {
        const uint32_t hb = sb + H_OFF + (uint32_t)((u % 3) * HBUF_B);
#pragma unroll
        for (int k = 0; k < 4; k++) {
            int hrow = hrow0 + k * 16;
            cpa16(hb + (uint32_t)((hrow * HPITCH + hseg) * 2),
                  hgb + (size_t)(u * BJ + hrow) * FO + hseg);
        }
    };
    auto issue_adj = [&](int u) {
        const uint32_t ab = sb + ADJ_OFF + (uint32_t)((u % 3) * ASTAGE_B);
#pragma unroll
        for (int ps = 0; ps < 8; ps++) {
            int row = ps * 8 + ry;
            cpa16(ab + (uint32_t)((row * APITCH + cx * 4) * 4),
                  adjb + (size_t)(ps * 8) * NN + u * BJ);
        }
    };

    // -------- prolog: hG0, adjG0, hG1, adjG1 --------
    issue_h(0);   cpa_commit();
    issue_adj(0); cpa_commit();
    issue_h(1);   cpa_commit();
    issue_adj(1); cpa_commit();

    for (int t = 0; t < NT; t++) {
        __syncthreads();              // B1: prev MMA reads done; safe to overwrite buffers

        const int u = t + 2;
        if (u < NT) issue_h(u);
        cpa_commit();                 // hG(t+2)
        if (u < NT) issue_adj(u);
        cpa_commit();                 // adjG(t+2)

        cpa_wait4();                  // hG(t), adjG(t) complete (this thread)

        // ---- p tile (64x64) from adj stage t%3 ----
        const int* astage = adj_sm + (t % 3) * ASTAGE_I;
        float4 pa = *(const float4*)(pq2b + t * BJ + cx * 4);
        float4 pb = *(const float4*)(pq2b + t * BJ + cx * 4 + 2);
#pragma unroll
        for (int ps = 0; ps < 8; ps++) {
            int row = ps * 8 + ry;
            int4 av = *(const int4*)(astage + row * APITCH + cx * 4);
            float p0 = av.x ? fmaxf(P1f[ps] * pa.x, Q1f[ps] * pa.y) : 0.f;
            float p1 = av.y ? fmaxf(P1f[ps] * pa.z, Q1f[ps] * pa.w) : 0.f;
            float p2 = av.z ? fmaxf(P1f[ps] * pb.x, Q1f[ps] * pb.y) : 0.f;
            float p3 = av.w ? fmaxf(P1f[ps] * pb.z, Q1f[ps] * pb.w) : 0.f;
            __half2 q01 = __floats2half2_rn(p0, p1);
            __half2 q23 = __floats2half2_rn(p2, p3);
            uint2 pk;
            pk.x = reinterpret_cast<uint32_t&>(q01);
            pk.y = reinterpret_cast<uint32_t&>(q23);
            *reinterpret_cast<uint2*>(&p_sm[row * PPITCH + cx * 4]) = pk;
        }

        __syncthreads();              // B2: p_sm + h buffer visible to all

        // ---- MMA: acc += p @ h, rs += p @ ones ----
        const uint32_t b_addr = sb + H_OFF + (uint32_t)((t % 3) * HBUF_B) + b_off;
#pragma unroll
        for (int ks = 0; ks < 4; ks++) {
            uint32_t a0, a1, a2, a3;
            ldsm4(a0, a1, a2, a3, a_addr + ks * 32);
#pragma unroll
            for (int nt2 = 0; nt2 < 4; nt2++) {
                uint32_t b0, b1, b2, b3;
                ldsm4t(b0, b1, b2, b3, b_addr + (uint32_t)((ks * 16 * HPITCH + nt2 * 16) * 2));
                mma16816(acc[nt2 * 2],     a0, a1, a2, a3, b0, b1);
                mma16816(acc[nt2 * 2 + 1], a0, a1, a2, a3, b2, b3);
            }
            mma16816(rs, a0, a1, a2, a3, ones, ones);
        }
    }

    // ---- epilogue: divide by rowsum, elu, store ----
    float rlo = __shfl_sync(0xffffffffu, rs[0], lane & ~3);
    float rhi = __shfl_sync(0xffffffffu, rs[2], lane & ~3);
    float ilo = 1.f / rlo;
    float ihi = 1.f / rhi;

    const int r_lo = i0 + warp * 16 + (lane >> 2);
    float* ob = out + (size_t)b * NN * FO;
#pragma unroll
    for (int nt2 = 0; nt2 < 8; nt2++) {
        int col = nt2 * 8 + (lane & 3) * 2;
        float v0 = acc[nt2][0] * ilo;
        float v1 = acc[nt2][1] * ilo;
        float v2 = acc[nt2][2] * ihi;
        float v3 = acc[nt2][3] * ihi;
        v0 = v0 > 0.f ? v0 : expm1f(v0);
        v1 = v1 > 0.f ? v1 : expm1f(v1);
        v2 = v2 > 0.f ? v2 : expm1f(v2);
        v3 = v3 > 0.f ? v3 : expm1f(v3);
        *reinterpret_cast<float2*>(&ob[(size_t)r_lo * FO + col])       = make_float2(v0, v1);
        *reinterpret_cast<float2*>(&ob[(size_t)(r_lo + 8) * FO + col]) = make_float2(v2, v3);
    }
}

// ---------------------------------------------------------------------------
extern "C" void kernel_launch(void* const* d_in, const int* in_sizes, int n_in,
                              void* d_out, int out_size)
{
    const float* inp = (const float*)d_in[0];
    const int*   adj = (const int*)d_in[1];
    const float* W   = (const float*)d_in[2];
    const float* a   = (const float*)d_in[3];
    float* out = (float*)d_out;

    static bool attr_set = false;
    if (!attr_set) {
        cudaFuncSetAttribute(k_h, cudaFuncAttributeMaxDynamicSharedMemorySize, KH_SMEM);
        cudaFuncSetAttribute(k_attn, cudaFuncAttributeMaxDynamicSharedMemorySize, ATTN_SMEM);
        attr_set = true;
    }

    k_h<<<BB * NN / 64, 256, KH_SMEM>>>(inp, W, a);
    k_pq<<<BB, 512>>>();
    k_attn<<<BB * (NN / BI), 128, ATTN_SMEM>>>(adj, out);
}

// round 6
// speedup vs baseline: 1.9063x; 1.0083x over previous
#include <cuda_runtime.h>
#include <cuda_fp16.h>
#include <cstdint>

#define BB 8
#define NN 4096
#define FI 128
#define FO 64
#define BI 64
#define BJ 64
#define NT (NN / BJ)
#define PPITCH 72
#define HPITCH 72

// k_attn shared memory layout (dynamic): 2 adj stages + 2 h buffers + 1 p
#define APITCH   68                      // ints per adj row
#define ASTAGE_I (64 * APITCH)           // ints per adj stage
#define ASTAGE_B (ASTAGE_I * 4)          // 17408 bytes
#define HBUF_B   (64 * HPITCH * 2)       // 9216 bytes
#define ADJ_OFF  0
#define H_OFF    (2 * ASTAGE_B)          // 34816
#define P_OFF    (H_OFF + 2 * HBUF_B)    // 53248
#define ATTN_SMEM (P_OFF + BI * PPITCH * 2)  // 62464

// Scratch (static __device__ — no allocation allowed)
__device__ __half h_fp16[(size_t)BB * NN * FO];   // 4 MB
__device__ float  s1_g[BB * NN];
__device__ float  s2_g[BB * NN];
__device__ float2 pq1_g[BB * NN];                 // {P1, Q1} per (b,i)
__device__ float2 pq2_g[BB * NN];                 // {P2, Q2} per (b,j)

// ---------------------------------------------------------------------------
// Kernel A1: h = inp @ W (fp32, fp16 store), s1 = h@a1, s2 = h@a2
// ---------------------------------------------------------------------------
#define KH_IPITCH 132
#define KH_SMEM ((FI * FO + 64 * KH_IPITCH + 2 * FO) * 4)

__global__ __launch_bounds__(256) void k_h(const float* __restrict__ inp,
                                           const float* __restrict__ W,
                                           const float* __restrict__ a)
{
    extern __shared__ float sm_f[];
    float* W_sm   = sm_f;                       // 128*64
    float* inp_sm = sm_f + FI * FO;             // 64*132
    float* a_sm   = inp_sm + 64 * KH_IPITCH;    // 128

    const int tid = threadIdx.x;
    const int blk = blockIdx.x;                 // 0 .. BB*NN/64-1
    const int b   = blk / (NN / 64);
    const int i0  = (blk % (NN / 64)) * 64;

#pragma unroll
    for (int k = 0; k < 8; k++)
        ((float4*)W_sm)[tid + k * 256] = ((const float4*)W)[tid + k * 256];
    if (tid < 2 * FO) a_sm[tid] = a[tid];
    const float* inp_b = inp + ((size_t)b * NN + i0) * FI;
#pragma unroll
    for (int k = 0; k < 8; k++) {
        int c = tid + k * 256;
        int row = c >> 5, col = c & 31;
        *(float4*)(inp_sm + row * KH_IPITCH + col * 4) = ((const float4*)inp_b)[c];
    }
    __syncthreads();

    const int ox = tid & 15;
    const int rg = tid >> 4;
    const float4* Wv = (const float4*)W_sm;

    float4 acc[4];
#pragma unroll
    for (int k = 0; k < 4; k++) acc[k] = make_float4(0.f, 0.f, 0.f, 0.f);

#pragma unroll 4
    for (int f = 0; f < FI; f++) {
        float4 w = Wv[f * 16 + ox];
#pragma unroll
        for (int k = 0; k < 4; k++) {
            float x = inp_sm[(rg + 16 * k) * KH_IPITCH + f];
            acc[k].x += x * w.x; acc[k].y += x * w.y;
            acc[k].z += x * w.z; acc[k].w += x * w.w;
        }
    }

    const int o4 = ox * 4;
#pragma unroll
    for (int k = 0; k < 4; k++) {
        float s1p = acc[k].x * a_sm[o4] + acc[k].y * a_sm[o4 + 1]
                  + acc[k].z * a_sm[o4 + 2] + acc[k].w * a_sm[o4 + 3];
        float s2p = acc[k].x * a_sm[FO + o4] + acc[k].y * a_sm[FO + o4 + 1]
                  + acc[k].z * a_sm[FO + o4 + 2] + acc[k].w * a_sm[FO + o4 + 3];
#pragma unroll
        for (int m = 8; m >= 1; m >>= 1) {
            s1p += __shfl_xor_sync(0xffffffffu, s1p, m);
            s2p += __shfl_xor_sync(0xffffffffu, s2p, m);
        }
        const int grow = b * NN + i0 + rg + 16 * k;
        if (ox == 0) { s1_g[grow] = s1p; s2_g[grow] = s2p; }

        __half2 h01 = __floats2half2_rn(acc[k].x, acc[k].y);
        __half2 h23 = __floats2half2_rn(acc[k].z, acc[k].w);
        __half2* dst = (__half2*)(h_fp16 + (size_t)grow * FO + o4);
        dst[0] = h01; dst[1] = h23;
    }
}

// ---------------------------------------------------------------------------
// Kernel A2: exp factor tables.  exp(lrelu(s1+s2) - M/L) = max(P1*P2, Q1*Q2)
// ---------------------------------------------------------------------------
__global__ void k_pq()
{
    const int b = blockIdx.x;
    const int tid = threadIdx.x;      // 512 threads
    __shared__ float red[16];

    const float* s2b = s2_g + b * NN;
    float mx = -1e30f;
    for (int j = tid; j < NN; j += 512) mx = fmaxf(mx, s2b[j]);
#pragma unroll
    for (int m = 16; m >= 1; m >>= 1)
        mx = fmaxf(mx, __shfl_xor_sync(0xffffffffu, mx, m));
    if ((tid & 31) == 0) red[tid >> 5] = mx;
    __syncthreads();
    if (tid == 0) {
        float v = red[0];
        for (int k = 1; k < 16; k++) v = fmaxf(v, red[k]);
        red[0] = v;
    }
    __syncthreads();

    const float L = 1.4426950408889634f;
    const float s2maxL = red[0] * L;
    for (int j = tid; j < NN; j += 512) {
        float sL = s2b[j] * L;
        pq2_g[b * NN + j] = make_float2(exp2f(sL), exp2f(0.2f * sL));
        float s1L = s1_g[b * NN + j] * L;
        float t = s1L + s2maxL;
        float M = fmaxf(t, 0.2f * t);
        pq1_g[b * NN + j] = make_float2(exp2f(s1L - M), exp2f(0.2f * s1L - M));
    }
}

// ---------------------------------------------------------------------------
// PTX helpers
// ---------------------------------------------------------------------------
__device__ __forceinline__ void ldsm4(uint32_t& r0, uint32_t& r1, uint32_t& r2, uint32_t& r3, uint32_t addr)
{
    asm volatile("ldmatrix.sync.aligned.m8n8.x4.shared.b16 {%0,%1,%2,%3}, [%4];"
                 : "=r"(r0), "=r"(r1), "=r"(r2), "=r"(r3) : "r"(addr));
}
__device__ __forceinline__ void ldsm4t(uint32_t& r0, uint32_t& r1, uint32_t& r2, uint32_t& r3, uint32_t addr)
{
    asm volatile("ldmatrix.sync.aligned.m8n8.x4.trans.shared.b16 {%0,%1,%2,%3}, [%4];"
                 : "=r"(r0), "=r"(r1), "=r"(r2), "=r"(r3) : "r"(addr));
}
__device__ __forceinline__ void mma16816(float* d, uint32_t a0, uint32_t a1, uint32_t a2, uint32_t a3,
                                         uint32_t b0, uint32_t b1)
{
    asm volatile("mma.sync.aligned.m16n8k16.row.col.f32.f16.f16.f32 "
                 "{%0,%1,%2,%3}, {%4,%5,%6,%7}, {%8,%9}, {%0,%1,%2,%3};"
                 : "+f"(d[0]), "+f"(d[1]), "+f"(d[2]), "+f"(d[3])
                 : "r"(a0), "r"(a1), "r"(a2), "r"(a3), "r"(b0), "r"(b1));
}
__device__ __forceinline__ void cpa16(uint32_t smem, const void* g)
{
    asm volatile("cp.async.cg.shared.global [%0], [%1], 16;" :: "r"(smem), "l"(g));
}
__device__ __forceinline__ void cpa_commit() { asm volatile("cp.async.commit_group;" ::: "memory"); }
__device__ __forceinline__ void cpa_wait1()  { asm volatile("cp.async.wait_group 1;" ::: "memory"); }

// ---------------------------------------------------------------------------
// Kernel B: fused mask + softmax(no-rescale) + PV matmul + elu.
// 512 CTAs x 256 threads (8 warps), 3 CTAs/SM (24 warps/SM).
//  - warp (wr=warp&3, ch=warp>>2): rows wr*16..+15, cols ch*32..+31.
//  - adj: 2-stage SMEM ring, "own-data" cp.async (no barrier needed for adj).
//  - h: 2 buffers. One combined cp.async group {h,adj} per iter, distance 1.
// ---------------------------------------------------------------------------
__global__ __launch_bounds__(256, 3) void k_attn(const int* __restrict__ adj,
                                                 float* __restrict__ out)
{
    extern __shared__ __align__(16) unsigned char smem[];
    const uint32_t sb = (uint32_t)__cvta_generic_to_shared(smem);
    int*    adj_sm = (int*)smem;                         // 2 stages
    __half* p_sm   = (__half*)(smem + P_OFF);

    const int tid  = threadIdx.x;
    const int lane = tid & 31;
    const int warp = tid >> 5;
    const int wr   = warp & 3;          // row group
    const int ch   = warp >> 2;         // col half
    const int blk  = blockIdx.x;        // 0..511
    const int b    = blk >> 6;
    const int i0   = (blk & 63) * BI;

    const int cx = tid & 15;            // 4 j-columns per thread
    const int ry = (tid >> 4) & 15;     // 0..15 row-in-group

    float acc[4][4];
    float rs[4];
#pragma unroll
    for (int t = 0; t < 4; t++)
#pragma unroll
        for (int k = 0; k < 4; k++) acc[t][k] = 0.f;
#pragma unroll
    for (int k = 0; k < 4; k++) rs[k] = 0.f;

    const uint32_t ones = (lane < 4) ? 0x3C003C00u : 0u;

    // per-row P1/Q1 (fixed for entire kernel) -> registers (rows ps*16 + ry)
    float P1f[4], Q1f[4];
    {
        const float2* pq1b = pq1_g + b * NN + i0;
#pragma unroll
        for (int ps = 0; ps < 4; ps++) {
            float2 pq = __ldg(&pq1b[ps * 16 + ry]);
            P1f[ps] = pq.x; Q1f[ps] = pq.y;
        }
    }

    const float2* pq2b = pq2_g + b * NN;
    const __half* hgb  = h_fp16 + (size_t)b * NN * FO;
    const int* adjb = adj + ((size_t)(b * NN + i0 + ry)) * NN + cx * 4;

    // h cp.async chunk coords (2 chunks/thread, 16B): chunk c = tid + k*256
    const int hrow0 = tid >> 3;        // 0..31
    const int hseg  = (tid & 7) * 8;   // halves

    // ldmatrix lane addressing
    const uint32_t a_addr = sb + P_OFF
        + (uint32_t)(((wr * 16 + (lane & 15)) * PPITCH + (lane >> 4) * 8) * 2);
    const uint32_t b_off = (uint32_t)(((lane & 15) * HPITCH + ch * 32 + (lane >> 4) * 8) * 2);

    auto issue = [&](int u) {
        const uint32_t hb = sb + H_OFF + (uint32_t)((u & 1) * HBUF_B);
#pragma unroll
        for (int k = 0; k < 2; k++) {
            int hrow = hrow0 + k * 32;
            cpa16(hb + (uint32_t)((hrow * HPITCH + hseg) * 2),
                  hgb + (size_t)(u * BJ + hrow) * FO + hseg);
        }
        const uint32_t ab = sb + ADJ_OFF + (uint32_t)((u & 1) * ASTAGE_B);
#pragma unroll
        for (int ps = 0; ps < 4; ps++) {
            int row = ps * 16 + ry;
            cpa16(ab + (uint32_t)((row * APITCH + cx * 4) * 4),
                  adjb + (size_t)(ps * 16) * NN + u * BJ);
        }
    };

    // -------- prolog: group 0 --------
    issue(0); cpa_commit();

    for (int t = 0; t < NT; t++) {
        __syncthreads();                   // B1: iter t-1 MMA reads done

        if (t + 1 < NT) issue(t + 1);
        cpa_commit();                      // group t+1 (possibly empty)
        cpa_wait1();                       // group t complete (own adj; own h chunks)

        // ---- p tile (64x64) from adj stage t&1 ----
        const int* astage = adj_sm + (t & 1) * ASTAGE_I;
        float4 pa = *(const float4*)(pq2b + t * BJ + cx * 4);
        float4 pb = *(const float4*)(pq2b + t * BJ + cx * 4 + 2);
#pragma unroll
        for (int ps = 0; ps < 4; ps++) {
            int row = ps * 16 + ry;
            int4 av = *(const int4*)(astage + row * APITCH + cx * 4);
            float p0 = av.x ? fmaxf(P1f[ps] * pa.x, Q1f[ps] * pa.y) : 0.f;
            float p1 = av.y ? fmaxf(P1f[ps] * pa.z, Q1f[ps] * pa.w) : 0.f;
            float p2 = av.z ? fmaxf(P1f[ps] * pb.x, Q1f[ps] * pb.y) : 0.f;
            float p3 = av.w ? fmaxf(P1f[ps] * pb.z, Q1f[ps] * pb.w) : 0.f;
            __half2 q01 = __floats2half2_rn(p0, p1);
            __half2 q23 = __floats2half2_rn(p2, p3);
            uint2 pk;
            pk.x = reinterpret_cast<uint32_t&>(q01);
            pk.y = reinterpret_cast<uint32_t&>(q23);
            *reinterpret_cast<uint2*>(&p_sm[row * PPITCH + cx * 4]) = pk;
        }

        __syncthreads();                   // B2: p_sm + h buffer visible to all

        // ---- MMA: acc += p @ h (warp's 16x32 slice), rs += p @ ones ----
        const uint32_t b_addr = sb + H_OFF + (uint32_t)((t & 1) * HBUF_B) + b_off;
#pragma unroll
        for (int ks = 0; ks < 4; ks++) {
            uint32_t a0, a1, a2, a3;
            ldsm4(a0, a1, a2, a3, a_addr + ks * 32);
#pragma unroll
            for (int nt2 = 0; nt2 < 2; nt2++) {
                uint32_t b0, b1, b2, b3;
                ldsm4t(b0, b1, b2, b3, b_addr + (uint32_t)((ks * 16 * HPITCH + nt2 * 16) * 2));
                mma16816(acc[nt2 * 2],     a0, a1, a2, a3, b0, b1);
                mma16816(acc[nt2 * 2 + 1], a0, a1, a2, a3, b2, b3);
            }
            mma16816(rs, a0, a1, a2, a3, ones, ones);
        }
    }

    // ---- epilogue: broadcast rowsum (col 0 lives in lane%4==0), divide, elu ----
    float rlo = __shfl_sync(0xffffffffu, rs[0], lane & ~3);
    float rhi = __shfl_sync(0xffffffffu, rs[2], lane & ~3);
    float ilo = 1.f / rlo;
    float ihi = 1.f / rhi;

    const int r_lo = i0 + wr * 16 + (lane >> 2);
    float* ob = out + (size_t)b * NN * FO;
#pragma unroll
    for (int t = 0; t < 4; t++) {
        int col = ch * 32 + t * 8 + (lane & 3) * 2;
        float v0 = acc[t][0] * ilo;
        float v1 = acc[t][1] * ilo;
        float v2 = acc[t][2] * ihi;
        float v3 = acc[t][3] * ihi;
        v0 = v0 > 0.f ? v0 : expm1f(v0);
        v1 = v1 > 0.f ? v1 : expm1f(v1);
        v2 = v2 > 0.f ? v2 : expm1f(v2);
        v3 = v3 > 0.f ? v3 : expm1f(v3);
        *reinterpret_cast<float2*>(&ob[(size_t)r_lo * FO + col])       = make_float2(v0, v1);
        *reinterpret_cast<float2*>(&ob[(size_t)(r_lo + 8) * FO + col]) = make_float2(v2, v3);
    }
}

// ---------------------------------------------------------------------------
extern "C" void kernel_launch(void* const* d_in, const int* in_sizes, int n_in,
                              void* d_out, int out_size)
{
    const float* inp = (const float*)d_in[0];
    const int*   adj = (const int*)d_in[1];
    const float* W   = (const float*)d_in[2];
    const float* a   = (const float*)d_in[3];
    float* out = (float*)d_out;

    static bool attr_set = false;
    if (!attr_set) {
        cudaFuncSetAttribute(k_h, cudaFuncAttributeMaxDynamicSharedMemorySize, KH_SMEM);
        cudaFuncSetAttribute(k_attn, cudaFuncAttributeMaxDynamicSharedMemorySize, ATTN_SMEM);
        attr_set = true;
    }

    k_h<<<BB * NN / 64, 256, KH_SMEM>>>(inp, W, a);
    k_pq<<<BB, 512>>>();
    k_attn<<<BB * (NN / BI), 256, ATTN_SMEM>>>(adj, out);
}